// round 11
// baseline (speedup 1.0000x reference)
#include <cuda_runtime.h>
#include <cstdint>
#include <cstddef>

#define NC    4
#define CC    64
#define DC    192
#define TPAD  196
#define GPAD  68
#define QQ    512
#define ND    (NC*DC)
#define IDIM  768
#define EPSF  1e-8f

__device__ float g_hatm[NC*CC*DC];
__device__ float g_hq[QQ*ND];
__device__ float g_G[NC*CC*CC];
__device__ float g_mu[NC*CC];
__device__ float g_sxx[NC*CC];

typedef unsigned long long u64;
__device__ __forceinline__ void f2unpack(u64 v, float& lo, float& hi) {
    asm("mov.b64 {%0, %1}, %2;" : "=f"(lo), "=f"(hi) : "l"(v));
}
__device__ __forceinline__ u64 f2dup(float a) {
    u64 r;
    asm("mov.b64 %0, {%1, %1};" : "=l"(r) : "f"(a));
    return r;
}
__device__ __forceinline__ u64 ffma2(u64 a, u64 b, u64 c) {
    u64 d;
    asm("fma.rn.f32x2 %0, %1, %2, %3;" : "=l"(d) : "l"(a), "l"(b), "l"(c));
    return d;
}
__device__ __forceinline__ u64 fadd2(u64 a, u64 b) {
    u64 d;
    asm("add.rn.f32x2 %0, %1, %2;" : "=l"(d) : "l"(a), "l"(b));
    return d;
}

// =============================================================================
// Kernel A: fused GEMM  C[576 x 768] = [m;q] @ Wl^T  (FFMA2; unchanged)
// =============================================================================
#define GBM 48
#define GBN 64
#define GKT 64
#define APAD 68

__global__ __launch_bounds__(256, 1)
void gemm_kernel(const float* __restrict__ Am, const float* __restrict__ Aq,
                 const float* __restrict__ W,  const float* __restrict__ Bb)
{
    __shared__ __align__(16) float As[GBM][APAD];
    __shared__ __align__(16) float Bs[GKT][GBN + 4];

    const int t   = threadIdx.x;
    const int tx  = t & 15;
    const int ty  = t >> 4;
    const int row0 = blockIdx.y * GBM;
    const int col0 = blockIdx.x * GBN;

    const float* aptr[3];
    int arow[3], acol[3];
#pragma unroll
    for (int j = 0; j < 3; j++) {
        const int i = t + 256 * j;
        arow[j] = i >> 4;
        acol[j] = (i & 15) << 2;
        const int rg = row0 + arow[j];
        aptr[j] = ((rg < 64) ? (Am + (size_t)rg * IDIM)
                             : (Aq + (size_t)(rg - 64) * IDIM)) + acol[j];
    }

    const int lb_j = t >> 2;
    const int lb_k = (t & 3) << 2;
    const int gj = col0 + lb_j;
    const int bn = gj / DC;
    const int bd = gj - bn * DC;
    const float* brow = W + ((size_t)bn * CC * DC + bd) * IDIM + lb_k;

    u64 acc[3][2];
#pragma unroll
    for (int i = 0; i < 3; i++) { acc[i][0] = 0ull; acc[i][1] = 0ull; }

    for (int kt = 0; kt < IDIM; kt += GKT) {
#pragma unroll
        for (int j = 0; j < 3; j++) {
            float4 a = *(const float4*)(aptr[j] + kt);
            *(float4*)&As[arow[j]][acol[j]] = a;
        }
#pragma unroll
        for (int c = 0; c < 4; c++) {
            float4 b = *(const float4*)(brow + kt + 16 * c);
            Bs[lb_k + 16 * c + 0][lb_j] = b.x;
            Bs[lb_k + 16 * c + 1][lb_j] = b.y;
            Bs[lb_k + 16 * c + 2][lb_j] = b.z;
            Bs[lb_k + 16 * c + 3][lb_j] = b.w;
        }
        __syncthreads();
#pragma unroll 16
        for (int k = 0; k < GKT; k++) {
            ulonglong2 bp = *(const ulonglong2*)&Bs[k][tx << 2];
            u64 a0 = f2dup(As[ty * 3 + 0][k]);
            u64 a1 = f2dup(As[ty * 3 + 1][k]);
            u64 a2 = f2dup(As[ty * 3 + 2][k]);
            acc[0][0] = ffma2(a0, bp.x, acc[0][0]);
            acc[0][1] = ffma2(a0, bp.y, acc[0][1]);
            acc[1][0] = ffma2(a1, bp.x, acc[1][0]);
            acc[1][1] = ffma2(a1, bp.y, acc[1][1]);
            acc[2][0] = ffma2(a2, bp.x, acc[2][0]);
            acc[2][1] = ffma2(a2, bp.y, acc[2][1]);
        }
        __syncthreads();
    }

    const int jb = col0 + (tx << 2);
#pragma unroll
    for (int i = 0; i < 3; i++) {
        const int r = row0 + ty * 3 + i;
        float v0, v1, v2, v3;
        f2unpack(acc[i][0], v0, v1);
        f2unpack(acc[i][1], v2, v3);
        if (r < 64) {
            float vv[4] = {v0, v1, v2, v3};
#pragma unroll
            for (int cj = 0; cj < 4; cj++) {
                const int j = jb + cj;
                const int n = j / DC;
                const int d = j - n * DC;
                const int idx = (n * CC + r) * DC + d;
                g_hatm[idx] = vv[cj] + Bb[idx];
            }
        } else {
            float4 o; o.x = v0; o.y = v1; o.z = v2; o.w = v3;
            *(float4*)(g_hq + (size_t)(r - 64) * ND + jb) = o;
        }
    }
}

// =============================================================================
// Kernel B: Gram + tm row stats.  grid 16 = (n, c2-quad)
// =============================================================================
__global__ __launch_bounds__(256, 1)
void prep_kernel()
{
    extern __shared__ float smB[];
    float* tm_s = smB;                      // [64][TPAD]
    const int n = blockIdx.x >> 2, quad = blockIdx.x & 3;
    const int t = threadIdx.x;

    for (int i = t; i < CC * 48; i += 256) {
        const int r = i / 48, d4 = (i % 48) << 2;
        *(float4*)&tm_s[r * TPAD + d4] =
            *(const float4*)&g_hatm[(size_t)(n * CC + r) * DC + d4];
    }
    __syncthreads();

    if (quad == 0 && t < CC) {
        const float* rp = tm_s + t * TPAD;
        float s = 0.f;
        for (int d = 0; d < DC; d += 4) {
            float4 v = *(const float4*)(rp + d);
            s += (v.x + v.y) + (v.z + v.w);
        }
        const float mu = s * (1.0f / DC);
        float ss = 0.f;
        for (int d = 0; d < DC; d += 4) {
            float4 v = *(const float4*)(rp + d);
            float e0 = v.x - mu, e1 = v.y - mu, e2 = v.z - mu, e3 = v.w - mu;
            ss += (e0 * e0 + e1 * e1) + (e2 * e2 + e3 * e3);
        }
        g_mu[n * CC + t] = mu; g_sxx[n * CC + t] = ss;
    }

    const int c1 = t & 63;
    const int c2b = quad * 16 + ((t >> 6) << 2);
    float acc[4] = {0.f, 0.f, 0.f, 0.f};
    for (int d4 = 0; d4 < DC; d4 += 4) {
        float4 x = *(const float4*)&tm_s[c1 * TPAD + d4];
#pragma unroll
        for (int j = 0; j < 4; j++) {
            float4 y = *(const float4*)&tm_s[(c2b + j) * TPAD + d4];
            acc[j] += (x.x * y.x + x.y * y.y) + (x.z * y.z + x.w * y.w);
        }
    }
    float4 o; o.x = acc[0]; o.y = acc[1]; o.z = acc[2]; o.w = acc[3];
    *(float4*)&g_G[(n * CC + c1) * CC + c2b] = o;
}

// =============================================================================
// Kernel C: FUSED dotq + route + out.  grid 128 x 256 thr; CTA owns 4 queries.
// Smem layout (floats):
//   G_s   [0      .. 17408)   [4*64][GPAD]
//   hq_s  [17408  .. 20480)   4 x 768          (dead after routing)
//   dq_s  [20480  .. 21504)   4 x 256          (dead after routing)
//   part  [17408  .. 23552)   2 x 4 x 768      (phase D, reuses hq/dq region)
//   co_s  [23552  .. 24576)   4 x 256
//   st_s  [24576  .. 24608)   S1[16], ss[16]
// =============================================================================
#define OFF_HQ   17408
#define OFF_DQ   20480
#define OFF_PART 17408
#define OFF_CO   23552
#define OFF_ST   24576
#define SMF_TOT  24608

__global__ __launch_bounds__(256, 1)
void fused_kernel(float* __restrict__ out)
{
    extern __shared__ float sm[];
    float* G_s  = sm;
    float* hq_s = sm + OFF_HQ;
    float* dq_s = sm + OFF_DQ;
    float* part = sm + OFF_PART;
    float* co_s = sm + OFF_CO;
    float* st_s = sm + OFF_ST;

    const int t = threadIdx.x, lane = t & 31, w = t >> 5;
    const int q0 = blockIdx.x * 4;

    // ---- Phase A: load G + 4 hq rows ----
    for (int i = t; i < NC * CC * 16; i += 256) {
        const int row = i >> 4, c4 = (i & 15) << 2;
        *(float4*)&G_s[row * GPAD + c4] = *(const float4*)&g_G[row * CC + c4];
    }
    for (int i = t; i < 768; i += 256) {          // 768 float4 = 4x768 floats
        const int q = i / 192, dd = (i % 192) << 2;
        *(float4*)&hq_s[q * ND + dd] =
            *(const float4*)&g_hq[(size_t)(q0 + q) * ND + dd];
    }
    __syncthreads();

    // ---- tq0 stats: 16 (q,n) pairs, 2 per warp ----
#pragma unroll
    for (int pp = 0; pp < 2; pp++) {
        const int pr = w * 2 + pp;
        const int q = pr >> 2, n = pr & 3;
        const float* hp = hq_s + q * ND + n * DC;
        float s = 0.f, sq = 0.f;
#pragma unroll
        for (int k = 0; k < 6; k++) { float x = hp[lane + 32 * k]; s += x; sq += x * x; }
#pragma unroll
        for (int o = 16; o > 0; o >>= 1) {
            s  += __shfl_xor_sync(0xffffffffu, s, o);
            sq += __shfl_xor_sync(0xffffffffu, sq, o);
        }
        if (lane == 0) { st_s[pr] = s; st_s[16 + pr] = sq; }
    }

    // ---- Phase B: dq0[q][n,c] = tm_row . hq_q ; warp = 32 rows ----
    for (int i = 0; i < 32; i++) {
        const int r = w * 32 + i;           // r = n*64+c
        const int n = r >> 6;
        const float* tp = g_hatm + (size_t)r * DC + lane * 2;
        const u64 t0 = *(const u64*)(tp);
        const u64 t1 = *(const u64*)(tp + 64);
        const u64 t2 = *(const u64*)(tp + 128);
        const float* hb = hq_s + n * DC + lane * 2;
        float v[4];
#pragma unroll
        for (int q = 0; q < 4; q++) {
            const float* hp = hb + q * ND;
            u64 a = 0ull;
            a = ffma2(t0, *(const u64*)(hp), a);
            a = ffma2(t1, *(const u64*)(hp + 64), a);
            a = ffma2(t2, *(const u64*)(hp + 128), a);
            float lo, hi; f2unpack(a, lo, hi);
            v[q] = lo + hi;
        }
#pragma unroll
        for (int o = 16; o > 0; o >>= 1) {
#pragma unroll
            for (int q = 0; q < 4; q++)
                v[q] += __shfl_xor_sync(0xffffffffu, v[q], o);
        }
        if (lane < 4) dq_s[lane * 256 + r] = v[lane];
    }
    __syncthreads();

    // ---- Phase C: routing (warps 0..3, one query each) ----
    if (w < 4) {
        float* co_w = co_s + w * 256;
        const float* dq_w = dq_s + w * 256;

        float mu[NC][2], sxx[NC][2], dq[NC][2], a[NC][2], p[NC][2], co[NC][2];
        float S1[NC], ss[NC];
#pragma unroll
        for (int n = 0; n < NC; n++) {
#pragma unroll
            for (int j = 0; j < 2; j++) {
                const int idx = n * CC + lane + 32 * j;
                mu[n][j]  = g_mu[idx];
                sxx[n][j] = g_sxx[idx];
                dq[n][j]  = dq_w[idx];
                a[n][j]   = 0.f;
            }
            S1[n] = st_s[w * 4 + n];
            ss[n] = st_s[16 + w * 4 + n];
            const float syy = ss[n] - S1[n] * S1[n] * (1.0f / DC);
#pragma unroll
            for (int j = 0; j < 2; j++)
                p[n][j] = tanhf(-(dq[n][j] - mu[n][j] * S1[n])
                                * rsqrtf(sxx[n][j] * syy + EPSF));
        }

#pragma unroll 1
        for (int it = 0; it < 3; it++) {
#pragma unroll
            for (int j = 0; j < 2; j++) {
                float mx = fmaxf(fmaxf(a[0][j], a[1][j]), fmaxf(a[2][j], a[3][j]));
                float e0 = expf(a[0][j] - mx), e1 = expf(a[1][j] - mx);
                float e2 = expf(a[2][j] - mx), e3 = expf(a[3][j] - mx);
                float inv = 1.0f / (e0 + e1 + e2 + e3);
                co[0][j] = e0 * inv + p[0][j];
                co[1][j] = e1 * inv + p[1][j];
                co[2][j] = e2 * inv + p[2][j];
                co[3][j] = e3 * inv + p[3][j];
            }
#pragma unroll
            for (int n = 0; n < NC; n++) {
                co_w[n * CC + lane]      = co[n][0];
                co_w[n * CC + lane + 32] = co[n][1];
            }
            __syncwarp();

            float gc[NC][2];
#pragma unroll
            for (int n = 0; n < NC; n++) {
                const float* r0 = &G_s[(n * CC + lane) * GPAD];
                const float* r1 = &G_s[(n * CC + lane + 32) * GPAD];
                const float* cw = co_w + n * CC;
                float a0 = 0.f, a1 = 0.f;
#pragma unroll
                for (int c = 0; c < CC; c += 4) {
                    float4 cv = *(const float4*)(cw + c);
                    float4 g0 = *(const float4*)(r0 + c);
                    float4 g1 = *(const float4*)(r1 + c);
                    a0 += (cv.x * g0.x + cv.y * g0.y) + (cv.z * g0.z + cv.w * g0.w);
                    a1 += (cv.x * g1.x + cv.y * g1.y) + (cv.z * g1.z + cv.w * g1.w);
                }
                gc[n][0] = a0; gc[n][1] = a1;
            }

            float rS[NC], rD[NC], rM[NC];
#pragma unroll
            for (int n = 0; n < NC; n++) {
                rS[n] = co[n][0] * gc[n][0] + co[n][1] * gc[n][1];
                rD[n] = co[n][0] * dq[n][0] + co[n][1] * dq[n][1];
                rM[n] = co[n][0] * mu[n][0] + co[n][1] * mu[n][1];
            }
#pragma unroll
            for (int o = 16; o > 0; o >>= 1)
#pragma unroll
                for (int n = 0; n < NC; n++) {
                    rS[n] += __shfl_xor_sync(0xffffffffu, rS[n], o);
                    rD[n] += __shfl_xor_sync(0xffffffffu, rD[n], o);
                    rM[n] += __shfl_xor_sync(0xffffffffu, rM[n], o);
                }

            if (it == 2) {
#pragma unroll
                for (int n = 0; n < NC; n++) {
                    const float s = rS[n];
                    const float scale = s / ((1.0f + s) * sqrtf(s + EPSF));
                    co_w[n * CC + lane]      = co[n][0] * scale;
                    co_w[n * CC + lane + 32] = co[n][1] * scale;
                }
                break;
            }

#pragma unroll
            for (int n = 0; n < NC; n++) {
                const float s = rS[n];
                const float scale = s / ((1.0f + s) * sqrtf(s + EPSF));
                const float S1n = 0.5f * (S1[n] + scale * (float)DC * rM[n]);
                const float ssn = 0.25f * (ss[n] + 2.0f * scale * rD[n]
                                           + scale * scale * s);
#pragma unroll
                for (int j = 0; j < 2; j++) {
                    const float ag = scale * gc[n][j];
                    a[n][j] += p[n][j] * ag;
                    dq[n][j] = 0.5f * (dq[n][j] + ag);
                }
                S1[n] = S1n; ss[n] = ssn;
                const float syy = ssn - S1n * S1n * (1.0f / DC);
#pragma unroll
                for (int j = 0; j < 2; j++)
                    p[n][j] = tanhf(-(dq[n][j] - mu[n][j] * S1n)
                                    * rsqrtf(sxx[n][j] * syy + EPSF));
            }
            __syncwarp();
        }
    }
    __syncthreads();   // co_s ready; hq_s/dq_s now dead

    // ---- Phase D: out[4q][768] = co . tm ; warp = (n, c-half); tm read once ----
    {
        const int n = w >> 1, ch = w & 1;
        u64 acc[4][3];
#pragma unroll
        for (int q = 0; q < 4; q++)
#pragma unroll
            for (int k = 0; k < 3; k++) acc[q][k] = 0ull;

        const float* cb = co_s + n * CC + ch * 32;
        for (int i = 0; i < 32; i++) {
            const float* tp = g_hatm + (size_t)(n * CC + ch * 32 + i) * DC + lane * 2;
            const u64 t0 = *(const u64*)(tp);
            const u64 t1 = *(const u64*)(tp + 64);
            const u64 t2 = *(const u64*)(tp + 128);
#pragma unroll
            for (int q = 0; q < 4; q++) {
                const u64 wd = f2dup(cb[q * 256 + i]);
                acc[q][0] = ffma2(wd, t0, acc[q][0]);
                acc[q][1] = ffma2(wd, t1, acc[q][1]);
                acc[q][2] = ffma2(wd, t2, acc[q][2]);
            }
        }
        // store partials: part[(ch*4+q)*768 + n*192 + k*64 + lane*2]
#pragma unroll
        for (int q = 0; q < 4; q++)
#pragma unroll
            for (int k = 0; k < 3; k++)
                *(u64*)&part[(ch * 4 + q) * ND + n * DC + k * 64 + lane * 2] = acc[q][k];
    }
    __syncthreads();

    // combine halves + store: 1536 f2 elements, 6 per thread
#pragma unroll
    for (int j = 0; j < 6; j++) {
        const int idx2 = j * 256 + t;                 // f2 index in [0,1536)
        const u64 A = *(const u64*)&part[idx2 * 2];
        const u64 B = *(const u64*)&part[4 * ND + idx2 * 2];
        const u64 R = fadd2(A, B);
        float lo, hi; f2unpack(R, lo, hi);
        *(float2*)(out + (size_t)q0 * ND + idx2 * 2) = make_float2(lo, hi);
    }
}

// =============================================================================
// launch
// =============================================================================
extern "C" void kernel_launch(void* const* d_in, const int* in_sizes, int n_in,
                              void* d_out, int out_size)
{
    const float* m = (const float*)d_in[0];
    const float* q = (const float*)d_in[1];
    const float* W = (const float*)d_in[2];
    const float* b = (const float*)d_in[3];
    float* out = (float*)d_out;
    (void)in_sizes; (void)n_in; (void)out_size;

    const int smB = CC * TPAD * 4;          // 50176
    const int smF = SMF_TOT * 4;            // 98432
    cudaFuncSetAttribute(prep_kernel,  cudaFuncAttributeMaxDynamicSharedMemorySize, smB);
    cudaFuncSetAttribute(fused_kernel, cudaFuncAttributeMaxDynamicSharedMemorySize, smF);

    gemm_kernel<<<dim3(12, 12), 256>>>(m, q, W, b);
    prep_kernel<<<16, 256, smB>>>();
    fused_kernel<<<128, 256, smF>>>(out);
}

// round 12
// speedup vs baseline: 1.2224x; 1.2224x over previous
#include <cuda_runtime.h>
#include <cstdint>
#include <cstddef>

#define NC    4
#define CC    64
#define DC    192
#define TPAD  196
#define GPAD  68
#define QQ    512
#define ND    (NC*DC)
#define IDIM  768
#define EPSF  1e-8f
#define SQ194 194

__device__ float g_hatm[NC*CC*DC];
__device__ float g_hq[QQ*ND];
__device__ float g_G[NC*CC*CC];
__device__ float g_mu[NC*CC];
__device__ float g_sxx[NC*CC];
__device__ float g_dq0[QQ*NC*CC];
__device__ float g_S1[QQ*NC];
__device__ float g_ss[QQ*NC];
__device__ float g_co[QQ*NC*CC];

typedef unsigned long long u64;
__device__ __forceinline__ void f2unpack(u64 v, float& lo, float& hi) {
    asm("mov.b64 {%0, %1}, %2;" : "=f"(lo), "=f"(hi) : "l"(v));
}
__device__ __forceinline__ u64 f2dup(float a) {
    u64 r;
    asm("mov.b64 %0, {%1, %1};" : "=l"(r) : "f"(a));
    return r;
}
__device__ __forceinline__ u64 ffma2(u64 a, u64 b, u64 c) {
    u64 d;
    asm("fma.rn.f32x2 %0, %1, %2, %3;" : "=l"(d) : "l"(a), "l"(b), "l"(c));
    return d;
}

// =============================================================================
// Kernel A: fused GEMM  C[576 x 768] = [m;q] @ Wl^T  (FFMA2)
// DOUBLE-BUFFERED: LDG for tile i+1 issued before the FFMA2 block of tile i,
// STS after compute (data arrived), so L2/DRAM latency is fully hidden.
// Dynamic smem: 2 x (As 48x68 + Bs 64x68) = 60928 B.
// =============================================================================
#define GBM 48
#define GBN 64
#define GKT 64
#define APAD 68
#define ABUF (GBM*APAD)            // 3264 floats
#define BBUF (GKT*(GBN+4))         // 4352 floats
#define TILEBUF (ABUF + BBUF)      // 7616 floats per stage

__global__ __launch_bounds__(256, 1)
void gemm_kernel(const float* __restrict__ Am, const float* __restrict__ Aq,
                 const float* __restrict__ W,  const float* __restrict__ Bb)
{
    extern __shared__ __align__(16) float smG[];

    const int t   = threadIdx.x;
    const int tx  = t & 15;
    const int ty  = t >> 4;
    const int row0 = blockIdx.y * GBM;
    const int col0 = blockIdx.x * GBN;

    // A loader: 3 float4 per thread covering the 48x64 tile
    const float* aptr[3];
    int arow[3], acol[3];
#pragma unroll
    for (int j = 0; j < 3; j++) {
        const int i = t + 256 * j;
        arow[j] = i >> 4;
        acol[j] = (i & 15) << 2;
        const int rg = row0 + arow[j];
        aptr[j] = ((rg < 64) ? (Am + (size_t)rg * IDIM)
                             : (Aq + (size_t)(rg - 64) * IDIM)) + acol[j];
    }

    // B loader: 4 float4 per thread (one W row segment of 64 k)
    const int lb_j = t >> 2;
    const int lb_k = (t & 3) << 2;
    const int gj = col0 + lb_j;
    const int bn = gj / DC;
    const int bd = gj - bn * DC;
    const float* brow = W + ((size_t)bn * CC * DC + bd) * IDIM + lb_k;

    // ---- prologue: tile 0 -> buf 0 ----
    {
        float* As = smG;
        float* Bs = smG + ABUF;
#pragma unroll
        for (int j = 0; j < 3; j++) {
            float4 a = *(const float4*)(aptr[j]);
            *(float4*)&As[arow[j] * APAD + acol[j]] = a;
        }
#pragma unroll
        for (int c = 0; c < 4; c++) {
            float4 b = *(const float4*)(brow + 16 * c);
            Bs[(lb_k + 16 * c + 0) * (GBN + 4) + lb_j] = b.x;
            Bs[(lb_k + 16 * c + 1) * (GBN + 4) + lb_j] = b.y;
            Bs[(lb_k + 16 * c + 2) * (GBN + 4) + lb_j] = b.z;
            Bs[(lb_k + 16 * c + 3) * (GBN + 4) + lb_j] = b.w;
        }
    }
    __syncthreads();

    u64 acc[3][2];
#pragma unroll
    for (int i = 0; i < 3; i++) { acc[i][0] = 0ull; acc[i][1] = 0ull; }

#pragma unroll 1
    for (int it = 0; it < IDIM / GKT; it++) {
        const float* Asc = smG + (it & 1) * TILEBUF;
        const float* Bsc = Asc + ABUF;

        // prefetch next tile into registers (latency overlapped with compute)
        float4 ar0, ar1, ar2, br0, br1, br2, br3;
        const bool pf = (it < IDIM / GKT - 1);
        if (pf) {
            const int kt = (it + 1) * GKT;
            ar0 = *(const float4*)(aptr[0] + kt);
            ar1 = *(const float4*)(aptr[1] + kt);
            ar2 = *(const float4*)(aptr[2] + kt);
            br0 = *(const float4*)(brow + kt);
            br1 = *(const float4*)(brow + kt + 16);
            br2 = *(const float4*)(brow + kt + 32);
            br3 = *(const float4*)(brow + kt + 48);
        }

#pragma unroll 16
        for (int k = 0; k < GKT; k++) {
            ulonglong2 bp = *(const ulonglong2*)&Bsc[k * (GBN + 4) + (tx << 2)];
            u64 a0 = f2dup(Asc[(ty * 3 + 0) * APAD + k]);
            u64 a1 = f2dup(Asc[(ty * 3 + 1) * APAD + k]);
            u64 a2 = f2dup(Asc[(ty * 3 + 2) * APAD + k]);
            acc[0][0] = ffma2(a0, bp.x, acc[0][0]);
            acc[0][1] = ffma2(a0, bp.y, acc[0][1]);
            acc[1][0] = ffma2(a1, bp.x, acc[1][0]);
            acc[1][1] = ffma2(a1, bp.y, acc[1][1]);
            acc[2][0] = ffma2(a2, bp.x, acc[2][0]);
            acc[2][1] = ffma2(a2, bp.y, acc[2][1]);
        }
        __syncthreads();   // all warps done reading the buffer we now overwrite

        if (pf) {
            float* Asn = smG + ((it + 1) & 1) * TILEBUF;
            float* Bsn = Asn + ABUF;
            *(float4*)&Asn[arow[0] * APAD + acol[0]] = ar0;
            *(float4*)&Asn[arow[1] * APAD + acol[1]] = ar1;
            *(float4*)&Asn[arow[2] * APAD + acol[2]] = ar2;
            Bsn[(lb_k + 0) * (GBN + 4) + lb_j]  = br0.x;
            Bsn[(lb_k + 1) * (GBN + 4) + lb_j]  = br0.y;
            Bsn[(lb_k + 2) * (GBN + 4) + lb_j]  = br0.z;
            Bsn[(lb_k + 3) * (GBN + 4) + lb_j]  = br0.w;
            Bsn[(lb_k + 16) * (GBN + 4) + lb_j] = br1.x;
            Bsn[(lb_k + 17) * (GBN + 4) + lb_j] = br1.y;
            Bsn[(lb_k + 18) * (GBN + 4) + lb_j] = br1.z;
            Bsn[(lb_k + 19) * (GBN + 4) + lb_j] = br1.w;
            Bsn[(lb_k + 32) * (GBN + 4) + lb_j] = br2.x;
            Bsn[(lb_k + 33) * (GBN + 4) + lb_j] = br2.y;
            Bsn[(lb_k + 34) * (GBN + 4) + lb_j] = br2.z;
            Bsn[(lb_k + 35) * (GBN + 4) + lb_j] = br2.w;
            Bsn[(lb_k + 48) * (GBN + 4) + lb_j] = br3.x;
            Bsn[(lb_k + 49) * (GBN + 4) + lb_j] = br3.y;
            Bsn[(lb_k + 50) * (GBN + 4) + lb_j] = br3.z;
            Bsn[(lb_k + 51) * (GBN + 4) + lb_j] = br3.w;
        }
        __syncthreads();   // writes visible before next compute
    }

    const int jb = col0 + (tx << 2);
#pragma unroll
    for (int i = 0; i < 3; i++) {
        const int r = row0 + ty * 3 + i;
        float v0, v1, v2, v3;
        f2unpack(acc[i][0], v0, v1);
        f2unpack(acc[i][1], v2, v3);
        if (r < 64) {
            float vv[4] = {v0, v1, v2, v3};
#pragma unroll
            for (int cj = 0; cj < 4; cj++) {
                const int j = jb + cj;
                const int n = j / DC;
                const int d = j - n * DC;
                const int idx = (n * CC + r) * DC + d;
                g_hatm[idx] = vv[cj] + Bb[idx];
            }
        } else {
            float4 o; o.x = v0; o.y = v1; o.z = v2; o.w = v3;
            *(float4*)(g_hq + (size_t)(r - 64) * ND + jb) = o;
        }
    }
}

// =============================================================================
// Kernel B: merged prep + dotq (R9, unchanged).  grid 144.
// =============================================================================
__global__ __launch_bounds__(256, 1)
void prep_dotq_kernel()
{
    extern __shared__ float smP[];
    const int bx = blockIdx.x, t = threadIdx.x;

    if (bx < 128) {
        const int ch = bx & 1, n = (bx >> 1) & 3, qt = bx >> 3;
        float* hq_s = smP;                    // [32][194]
        float* tm_s = smP + 32 * SQ194;       // [32][194]
        float* red  = smP + 64 * SQ194;       // 512

        for (int i = t; i < 32 * 48; i += 256) {
            const int q = i / 48, d4 = (i % 48) << 2;
            float4 v = *(const float4*)&g_hq[(size_t)(qt * 32 + q) * ND + n * DC + d4];
            *(float2*)&hq_s[q * SQ194 + d4]     = make_float2(v.x, v.y);
            *(float2*)&hq_s[q * SQ194 + d4 + 2] = make_float2(v.z, v.w);
        }
        for (int i = t; i < 32 * 48; i += 256) {
            const int c = i / 48, d4 = (i % 48) << 2;
            float4 v = *(const float4*)&g_hatm[(size_t)(n * CC + ch * 32 + c) * DC + d4];
            *(float2*)&tm_s[c * SQ194 + d4]     = make_float2(v.x, v.y);
            *(float2*)&tm_s[c * SQ194 + d4 + 2] = make_float2(v.z, v.w);
        }
        __syncthreads();

        const int qg = t & 15, cg = t >> 4;
        const float* hq0 = hq_s + qg * SQ194;
        const float* hq1 = hq_s + (qg + 16) * SQ194;
        const float* tm0 = tm_s + cg * SQ194;
        const float* tm1 = tm_s + (cg + 16) * SQ194;
        u64 a00 = 0ull, a01 = 0ull, a10 = 0ull, a11 = 0ull;
#pragma unroll 8
        for (int k2 = 0; k2 < 96; k2++) {
            const u64 h0 = *(const u64*)(hq0 + k2 * 2);
            const u64 h1 = *(const u64*)(hq1 + k2 * 2);
            const u64 t0 = *(const u64*)(tm0 + k2 * 2);
            const u64 t1 = *(const u64*)(tm1 + k2 * 2);
            a00 = ffma2(h0, t0, a00);
            a01 = ffma2(h0, t1, a01);
            a10 = ffma2(h1, t0, a10);
            a11 = ffma2(h1, t1, a11);
        }
        const int qb = qt * 32, cb = n * CC + ch * 32;
        float lo, hi;
        f2unpack(a00, lo, hi); g_dq0[(size_t)(qb + qg)      * 256 + cb + cg]      = lo + hi;
        f2unpack(a01, lo, hi); g_dq0[(size_t)(qb + qg)      * 256 + cb + cg + 16] = lo + hi;
        f2unpack(a10, lo, hi); g_dq0[(size_t)(qb + qg + 16) * 256 + cb + cg]      = lo + hi;
        f2unpack(a11, lo, hi); g_dq0[(size_t)(qb + qg + 16) * 256 + cb + cg + 16] = lo + hi;

        if (ch == 0) {
            const int q = t >> 3, seg = t & 7;
            float s = 0.f, sq = 0.f;
            const float* hp = hq_s + q * SQ194 + seg * 24;
#pragma unroll
            for (int k = 0; k < 12; k++) {
                float2 v = *(const float2*)(hp + 2 * k);
                s  += v.x + v.y;
                sq += v.x * v.x + v.y * v.y;
            }
            red[t] = s;
            red[256 + t] = sq;
            __syncthreads();
            if (t < 32) {
                float S = 0.f, SQ = 0.f;
#pragma unroll
                for (int c = 0; c < 8; c++) {
                    S  += red[t * 8 + c];
                    SQ += red[256 + t * 8 + c];
                }
                g_S1[(qt * 32 + t) * NC + n] = S;
                g_ss[(qt * 32 + t) * NC + n] = SQ;
            }
        }
    } else {
        const int idx = bx - 128;
        const int n = idx >> 2, quad = idx & 3;
        float* tm_s = smP;                    // [64][TPAD]

        for (int i = t; i < CC * 48; i += 256) {
            const int r = i / 48, d4 = (i % 48) << 2;
            *(float4*)&tm_s[r * TPAD + d4] =
                *(const float4*)&g_hatm[(size_t)(n * CC + r) * DC + d4];
        }
        __syncthreads();

        if (quad == 0 && t < CC) {
            const float* rp = tm_s + t * TPAD;
            float s = 0.f;
            for (int d = 0; d < DC; d += 4) {
                float4 v = *(const float4*)(rp + d);
                s += (v.x + v.y) + (v.z + v.w);
            }
            const float mu = s * (1.0f / DC);
            float ss = 0.f;
            for (int d = 0; d < DC; d += 4) {
                float4 v = *(const float4*)(rp + d);
                float e0 = v.x - mu, e1 = v.y - mu, e2 = v.z - mu, e3 = v.w - mu;
                ss += (e0 * e0 + e1 * e1) + (e2 * e2 + e3 * e3);
            }
            g_mu[n * CC + t] = mu; g_sxx[n * CC + t] = ss;
        }

        const int c1 = t & 63;
        const int c2b = quad * 16 + ((t >> 6) << 2);
        float acc[4] = {0.f, 0.f, 0.f, 0.f};
        for (int d4 = 0; d4 < DC; d4 += 4) {
            float4 x = *(const float4*)&tm_s[c1 * TPAD + d4];
#pragma unroll
            for (int j = 0; j < 4; j++) {
                float4 y = *(const float4*)&tm_s[(c2b + j) * TPAD + d4];
                acc[j] += (x.x * y.x + x.y * y.y) + (x.z * y.z + x.w * y.w);
            }
        }
        float4 o; o.x = acc[0]; o.y = acc[1]; o.z = acc[2]; o.w = acc[3];
        *(float4*)&g_G[(n * CC + c1) * CC + c2b] = o;
    }
}

// =============================================================================
// Kernel C: routing core (R9, unchanged).  grid 128 x 128 thr.
// =============================================================================
__global__ __launch_bounds__(128, 1)
void route_kernel()
{
    extern __shared__ float smD[];
    float* G_s  = smD;                      // [4*64][GPAD]
    float* co_s = smD + NC * CC * GPAD;     // 4 * 256

    const int t = threadIdx.x, lane = t & 31, w = t >> 5;
    for (int i = t; i < NC * CC * 16; i += 128) {
        const int row = i >> 4, c4 = (i & 15) << 2;
        *(float4*)&G_s[row * GPAD + c4] = *(const float4*)&g_G[row * CC + c4];
    }
    __syncthreads();

    const int q = blockIdx.x * 4 + w;
    float* co_w = co_s + w * 256;

    float mu[NC][2], sxx[NC][2], dq[NC][2], a[NC][2], p[NC][2], co[NC][2];
    float S1[NC], ss[NC];
#pragma unroll
    for (int n = 0; n < NC; n++) {
#pragma unroll
        for (int j = 0; j < 2; j++) {
            const int idx = n * CC + lane + 32 * j;
            mu[n][j]  = g_mu[idx];
            sxx[n][j] = g_sxx[idx];
            dq[n][j]  = g_dq0[q * 256 + idx];
            a[n][j]   = 0.f;
        }
        S1[n] = g_S1[q * NC + n];
        ss[n] = g_ss[q * NC + n];
        const float syy = ss[n] - S1[n] * S1[n] * (1.0f / DC);
#pragma unroll
        for (int j = 0; j < 2; j++)
            p[n][j] = tanhf(-(dq[n][j] - mu[n][j] * S1[n])
                            * rsqrtf(sxx[n][j] * syy + EPSF));
    }

#pragma unroll 1
    for (int it = 0; it < 3; it++) {
#pragma unroll
        for (int j = 0; j < 2; j++) {
            float mx = fmaxf(fmaxf(a[0][j], a[1][j]), fmaxf(a[2][j], a[3][j]));
            float e0 = expf(a[0][j] - mx), e1 = expf(a[1][j] - mx);
            float e2 = expf(a[2][j] - mx), e3 = expf(a[3][j] - mx);
            float inv = 1.0f / (e0 + e1 + e2 + e3);
            co[0][j] = e0 * inv + p[0][j];
            co[1][j] = e1 * inv + p[1][j];
            co[2][j] = e2 * inv + p[2][j];
            co[3][j] = e3 * inv + p[3][j];
        }
#pragma unroll
        for (int n = 0; n < NC; n++) {
            co_w[n * CC + lane]      = co[n][0];
            co_w[n * CC + lane + 32] = co[n][1];
        }
        __syncwarp();

        float gc[NC][2];
#pragma unroll
        for (int n = 0; n < NC; n++) {
            const float* r0 = &G_s[(n * CC + lane) * GPAD];
            const float* r1 = &G_s[(n * CC + lane + 32) * GPAD];
            const float* cw = co_w + n * CC;
            float a0 = 0.f, a1 = 0.f;
#pragma unroll
            for (int c = 0; c < CC; c += 4) {
                float4 cv = *(const float4*)(cw + c);
                float4 g0 = *(const float4*)(r0 + c);
                float4 g1 = *(const float4*)(r1 + c);
                a0 += (cv.x * g0.x + cv.y * g0.y) + (cv.z * g0.z + cv.w * g0.w);
                a1 += (cv.x * g1.x + cv.y * g1.y) + (cv.z * g1.z + cv.w * g1.w);
            }
            gc[n][0] = a0; gc[n][1] = a1;
        }

        float rS[NC], rD[NC], rM[NC];
#pragma unroll
        for (int n = 0; n < NC; n++) {
            rS[n] = co[n][0] * gc[n][0] + co[n][1] * gc[n][1];
            rD[n] = co[n][0] * dq[n][0] + co[n][1] * dq[n][1];
            rM[n] = co[n][0] * mu[n][0] + co[n][1] * mu[n][1];
        }
#pragma unroll
        for (int o = 16; o > 0; o >>= 1)
#pragma unroll
            for (int n = 0; n < NC; n++) {
                rS[n] += __shfl_xor_sync(0xffffffffu, rS[n], o);
                rD[n] += __shfl_xor_sync(0xffffffffu, rD[n], o);
                rM[n] += __shfl_xor_sync(0xffffffffu, rM[n], o);
            }

        if (it == 2) {
#pragma unroll
            for (int n = 0; n < NC; n++) {
                const float s = rS[n];
                const float scale = s / ((1.0f + s) * sqrtf(s + EPSF));
                g_co[q * 256 + n * CC + lane]      = co[n][0] * scale;
                g_co[q * 256 + n * CC + lane + 32] = co[n][1] * scale;
            }
            break;
        }

#pragma unroll
        for (int n = 0; n < NC; n++) {
            const float s = rS[n];
            const float scale = s / ((1.0f + s) * sqrtf(s + EPSF));
            const float S1n = 0.5f * (S1[n] + scale * (float)DC * rM[n]);
            const float ssn = 0.25f * (ss[n] + 2.0f * scale * rD[n] + scale * scale * s);
#pragma unroll
            for (int j = 0; j < 2; j++) {
                const float ag = scale * gc[n][j];
                a[n][j] += p[n][j] * ag;
                dq[n][j] = 0.5f * (dq[n][j] + ag);
            }
            S1[n] = S1n; ss[n] = ssn;
            const float syy = ssn - S1n * S1n * (1.0f / DC);
#pragma unroll
            for (int j = 0; j < 2; j++)
                p[n][j] = tanhf(-(dq[n][j] - mu[n][j] * S1n)
                                * rsqrtf(sxx[n][j] * syy + EPSF));
        }
        __syncwarp();
    }
}

// =============================================================================
// Kernel D: out GEMM (R9, unchanged).  grid (16,2,4), 256 thr.
// =============================================================================
__global__ __launch_bounds__(256, 1)
void out_kernel(float* __restrict__ out)
{
    __shared__ __align__(16) float tm_s[64 * 96];   // [c][96]
    __shared__ float co_s[64 * 34];                 // [c][34]

    const int qt = blockIdx.x, dh = blockIdx.y, n = blockIdx.z;
    const int t = threadIdx.x;

    for (int i = t; i < 64 * 24; i += 256) {
        const int c = i / 24, d4 = (i % 24) << 2;
        *(float4*)&tm_s[c * 96 + d4] =
            *(const float4*)&g_hatm[(size_t)(n * CC + c) * DC + dh * 96 + d4];
    }
    for (int i = t; i < 64 * 32; i += 256) {
        const int c = i & 63, q = i >> 6;
        co_s[c * 34 + q] = g_co[(size_t)(qt * 32 + q) * 256 + n * CC + c];
    }
    __syncthreads();

    const int dg = t & 15, qg = t >> 4;
    u64 acc[2][3];
#pragma unroll
    for (int j = 0; j < 2; j++)
#pragma unroll
        for (int k = 0; k < 3; k++) acc[j][k] = 0ull;

    const float* tb = tm_s + dg * 2;
    const float* cb = co_s + qg * 2;
#pragma unroll 8
    for (int k = 0; k < CC; k++) {
        const u64 cop = *(const u64*)(cb + k * 34);
        float c0, c1;
        f2unpack(cop, c0, c1);
        const u64 w0 = f2dup(c0), w1 = f2dup(c1);
        const float* tr = tb + k * 96;
        const u64 t0 = *(const u64*)(tr);
        const u64 t1 = *(const u64*)(tr + 32);
        const u64 t2 = *(const u64*)(tr + 64);
        acc[0][0] = ffma2(w0, t0, acc[0][0]);
        acc[0][1] = ffma2(w0, t1, acc[0][1]);
        acc[0][2] = ffma2(w0, t2, acc[0][2]);
        acc[1][0] = ffma2(w1, t0, acc[1][0]);
        acc[1][1] = ffma2(w1, t1, acc[1][1]);
        acc[1][2] = ffma2(w1, t2, acc[1][2]);
    }

#pragma unroll
    for (int j = 0; j < 2; j++) {
        float* op = out + (size_t)(qt * 32 + qg * 2 + j) * ND + n * DC + dh * 96 + dg * 2;
        float x0, x1;
        f2unpack(acc[j][0], x0, x1); *(float2*)(op)      = make_float2(x0, x1);
        f2unpack(acc[j][1], x0, x1); *(float2*)(op + 32) = make_float2(x0, x1);
        f2unpack(acc[j][2], x0, x1); *(float2*)(op + 64) = make_float2(x0, x1);
    }
}

// =============================================================================
// launch
// =============================================================================
extern "C" void kernel_launch(void* const* d_in, const int* in_sizes, int n_in,
                              void* d_out, int out_size)
{
    const float* m = (const float*)d_in[0];
    const float* q = (const float*)d_in[1];
    const float* W = (const float*)d_in[2];
    const float* b = (const float*)d_in[3];
    float* out = (float*)d_out;
    (void)in_sizes; (void)n_in; (void)out_size;

    const int smG = 2 * TILEBUF * 4;                        // 60928
    const int smP = (64 * SQ194 + 512) * 4;                 // 51712
    const int smD = (NC * CC * GPAD + 4 * 256) * 4;         // 73728
    cudaFuncSetAttribute(gemm_kernel, cudaFuncAttributeMaxDynamicSharedMemorySize, smG);
    cudaFuncSetAttribute(prep_dotq_kernel, cudaFuncAttributeMaxDynamicSharedMemorySize, smP);
    cudaFuncSetAttribute(route_kernel, cudaFuncAttributeMaxDynamicSharedMemorySize, smD);

    gemm_kernel<<<dim3(12, 12), 256, smG>>>(m, q, W, b);
    prep_dotq_kernel<<<144, 256, smP>>>();
    route_kernel<<<128, 128, smD>>>();
    out_kernel<<<dim3(16, 2, 4), 256>>>(out);
}